// round 2
// baseline (speedup 1.0000x reference)
#include <cuda_runtime.h>
#include <math.h>

#define BATCH 16384
#define DIMQ  512
#define ZPD   1024
#define HID   256
#define DTC   0.1f

// Scratch (device globals — no allocation allowed in kernel_launch)
__device__ float g_zp[BATCH * ZPD];   // [q | p] concatenated, 64 MB
__device__ float g_h1[BATCH * HID];   // tanh(zp@W1+b1)
__device__ float g_d2[BATCH * HID];   // dpre2 = (1-h2^2)*W3
__device__ float g_d1[BATCH * HID];   // dpre1 = (1-h1^2)*(dpre2@W2^T)

// ---------------------------------------------------------------------------
// Tiled SGEMM: C(M x N) = A(M x K) @ B, with B either K x N row-major (NN)
// or N x K row-major (NT, i.e. multiply by B^T of an N x K matrix).
// BM=BN=64, BK=16, TM=TN=4, 256 threads.
// Epilogues:
//   EPI 0: out[m*N+n] = tanh(acc + bias[n])                      (h1)
//   EPI 1: t = tanh(acc + bias[n]); out = (1-t*t)*w3[n]          (dpre2)
//   EPI 2: out = acc * (1 - h1[m*N+n]^2)                         (dpre1)
//   EPI 3: out[m*outLd + colOff + n] += coef * acc               (zp update)
// ---------------------------------------------------------------------------
template <int TRANSB, int EPI>
__global__ __launch_bounds__(256)
void gemm64(const float* __restrict__ A, int K,
            const float* __restrict__ Bm, int N,
            const float* __restrict__ bias,
            const float* __restrict__ w3,
            const float* __restrict__ h1,
            float* __restrict__ out,
            int outLd, int colOff, float coef)
{
    __shared__ float As[16][68];   // A stored transposed: As[k][m]; 68 keeps 16B align
    __shared__ float Bs[16][68];   // Bs[k][n]

    const int tid = threadIdx.x;
    const int tx = tid & 15;       // 0..15 -> n micro-tile
    const int ty = tid >> 4;       // 0..15 -> m micro-tile
    const int m0 = blockIdx.y * 64;
    const int n0 = blockIdx.x * 64;

    float acc[4][4] = {};

    for (int k0 = 0; k0 < K; k0 += 16) {
        // --- load A tile (64 x 16) -> As[k][m], one float4 per thread
        {
            const int row = tid >> 2;
            const int kq  = (tid & 3) * 4;
            const float4 av = *(const float4*)&A[(size_t)(m0 + row) * K + k0 + kq];
            As[kq + 0][row] = av.x;
            As[kq + 1][row] = av.y;
            As[kq + 2][row] = av.z;
            As[kq + 3][row] = av.w;
        }
        // --- load B tile (16 x 64) -> Bs[k][n]
        if (TRANSB) {
            const int n  = tid >> 2;
            const int kq = (tid & 3) * 4;
            const float4 bv = *(const float4*)&Bm[(size_t)(n0 + n) * K + k0 + kq];
            Bs[kq + 0][n] = bv.x;
            Bs[kq + 1][n] = bv.y;
            Bs[kq + 2][n] = bv.z;
            Bs[kq + 3][n] = bv.w;
        } else {
            const int k  = tid >> 4;
            const int nq = (tid & 15) * 4;
            const float4 bv = *(const float4*)&Bm[(size_t)(k0 + k) * N + n0 + nq];
            *(float4*)&Bs[k][nq] = bv;
        }
        __syncthreads();

        #pragma unroll
        for (int kk = 0; kk < 16; kk++) {
            const float4 a4 = *(const float4*)&As[kk][ty * 4];
            const float4 b4 = *(const float4*)&Bs[kk][tx * 4];
            const float av[4] = {a4.x, a4.y, a4.z, a4.w};
            const float bv[4] = {b4.x, b4.y, b4.z, b4.w};
            #pragma unroll
            for (int i = 0; i < 4; i++)
                #pragma unroll
                for (int j = 0; j < 4; j++)
                    acc[i][j] += av[i] * bv[j];
        }
        __syncthreads();
    }

    #pragma unroll
    for (int i = 0; i < 4; i++) {
        const int m = m0 + ty * 4 + i;
        #pragma unroll
        for (int j = 0; j < 4; j++) {
            const int n = n0 + tx * 4 + j;
            const float v = acc[i][j];
            if (EPI == 0) {
                out[(size_t)m * N + n] = tanhf(v + bias[n]);
            } else if (EPI == 1) {
                const float t = tanhf(v + bias[n]);
                out[(size_t)m * N + n] = (1.0f - t * t) * w3[n];
            } else if (EPI == 2) {
                const float hv = h1[(size_t)m * N + n];
                out[(size_t)m * N + n] = v * (1.0f - hv * hv);
            } else {
                out[(size_t)m * outLd + colOff + n] += coef * v;
            }
        }
    }
}

// zp[:, :512] = z ; zp[:, 512:] = 0
__global__ __launch_bounds__(256)
void init_zp(const float* __restrict__ z, float* __restrict__ zp)
{
    const int i = blockIdx.x * blockDim.x + threadIdx.x;   // over BATCH*DIMQ/4
    const int m = i / (DIMQ / 4);
    const int c = (i % (DIMQ / 4)) * 4;
    const float4 zv = *(const float4*)&z[(size_t)m * DIMQ + c];
    *(float4*)&zp[(size_t)m * ZPD + c] = zv;
    *(float4*)&zp[(size_t)m * ZPD + DIMQ + c] = make_float4(0.f, 0.f, 0.f, 0.f);
}

// out = zp[:, :512]
__global__ __launch_bounds__(256)
void write_out(const float* __restrict__ zp, float* __restrict__ out)
{
    const int i = blockIdx.x * blockDim.x + threadIdx.x;   // over BATCH*DIMQ/4
    const int m = i / (DIMQ / 4);
    const int c = (i % (DIMQ / 4)) * 4;
    *(float4*)&out[(size_t)m * DIMQ + c] = *(const float4*)&zp[(size_t)m * ZPD + c];
}

extern "C" void kernel_launch(void* const* d_in, const int* in_sizes, int n_in,
                              void* d_out, int out_size)
{
    const float* z  = (const float*)d_in[0];
    const float* W1 = (const float*)d_in[1];   // (1024, 256) row-major
    const float* b1 = (const float*)d_in[2];
    const float* W2 = (const float*)d_in[3];   // (256, 256)
    const float* b2 = (const float*)d_in[4];
    const float* W3 = (const float*)d_in[5];   // (256, 1)
    // d_in[6] = b3: constant offset, no gradient contribution.
    float* out = (float*)d_out;

    float *zp, *h1, *d2, *d1;
    cudaGetSymbolAddress((void**)&zp, g_zp);
    cudaGetSymbolAddress((void**)&h1, g_h1);
    cudaGetSymbolAddress((void**)&d2, g_d2);
    cudaGetSymbolAddress((void**)&d1, g_d1);

    const dim3 blk(256);
    const dim3 grid_cp((BATCH * DIMQ / 4) / 256);
    const dim3 gK1(HID / 64, BATCH / 64);    // N=256
    const dim3 gK23(HID / 64, BATCH / 64);   // N=256
    const dim3 gK4(DIMQ / 64, BATCH / 64);   // N=512

    init_zp<<<grid_cp, blk>>>(z, zp);

    for (int step = 0; step < 3; step++) {
        for (int call = 0; call < 3; call++) {
            // h1 = tanh(zp @ W1 + b1)
            gemm64<0, 0><<<gK1, blk>>>(zp, ZPD, W1, HID,
                                       b1, nullptr, nullptr, h1, 0, 0, 0.f);
            // dpre2 = (1 - tanh(h1@W2 + b2)^2) * W3
            gemm64<0, 1><<<gK23, blk>>>(h1, HID, W2, HID,
                                        b2, W3, nullptr, d2, 0, 0, 0.f);
            // dpre1 = (d2 @ W2^T) * (1 - h1^2)
            gemm64<1, 2><<<gK23, blk>>>(d2, HID, W2, HID,
                                        nullptr, nullptr, h1, d1, 0, 0, 0.f);
            // half-gradient + in-place leapfrog update:
            //   call 0,2: g_q = d1 @ W1[:512]^T  -> p -= 0.5*dt*g_q
            //   call 1  : g_p = d1 @ W1[512:]^T  -> q += dt*g_p
            if (call == 1) {
                gemm64<1, 3><<<gK4, blk>>>(d1, HID, W1 + (size_t)DIMQ * HID, DIMQ,
                                           nullptr, nullptr, nullptr,
                                           zp, ZPD, 0, DTC);
            } else {
                gemm64<1, 3><<<gK4, blk>>>(d1, HID, W1, DIMQ,
                                           nullptr, nullptr, nullptr,
                                           zp, ZPD, DIMQ, -0.5f * DTC);
            }
        }
    }

    write_out<<<grid_cp, blk>>>(zp, out);
}

// round 4
// speedup vs baseline: 2.3168x; 2.3168x over previous
#include <cuda_runtime.h>
#include <cuda_bf16.h>
#include <stdint.h>

#define BATCH 16384
#define DIMQ  512
#define ZPD   1024
#define HID   256
#define DTC   0.1f

#define BM 128
#define BN 128
#define BK 32
#define ROWB 80                         // 32 k * 2B = 64B, padded to 80B (conflict-free ldmatrix)
#define A_BYTES (BM * ROWB)             // 10240
#define B_BYTES (BN * ROWB)             // 10240
#define STG_BYTES (2 * A_BYTES + 2 * B_BYTES)   // 40960: Ah | Al | Bh | Bl
#define SMEM_SZ (2 * STG_BYTES)         // 81920 (double buffered)

// ---------------- device global scratch (no allocs allowed) ----------------
__device__ float         g_zp [BATCH * ZPD];                 // fp32 master [q|p]
__device__ __nv_bfloat16 g_zph[BATCH * ZPD], g_zpl[BATCH * ZPD];
__device__ __nv_bfloat16 g_h1h[BATCH * HID], g_h1l[BATCH * HID];
__device__ __nv_bfloat16 g_d2h[BATCH * HID], g_d2l[BATCH * HID];
__device__ __nv_bfloat16 g_d1h[BATCH * HID], g_d1l[BATCH * HID];
// weights: W1^T [256][1024], W2^T [256][256], W1 direct [1024][256], W2 direct [256][256]
__device__ __nv_bfloat16 g_W1th[HID * ZPD], g_W1tl[HID * ZPD];
__device__ __nv_bfloat16 g_W2th[HID * HID], g_W2tl[HID * HID];
__device__ __nv_bfloat16 g_W1dh[ZPD * HID], g_W1dl[ZPD * HID];
__device__ __nv_bfloat16 g_W2dh[HID * HID], g_W2dl[HID * HID];

// ---------------- helpers ----------------
__device__ __forceinline__ uint32_t smem_u32(const void* p) {
    uint32_t a;
    asm("{ .reg .u64 t; cvta.to.shared.u64 t, %1; cvt.u32.u64 %0, t; }" : "=r"(a) : "l"(p));
    return a;
}
__device__ __forceinline__ float tanh_fast(float x) {
    float y; asm("tanh.approx.f32 %0, %1;" : "=f"(y) : "f"(x)); return y;
}
__device__ __forceinline__ void cp16(uint32_t s, const void* g) {
    asm volatile("cp.async.cg.shared.global [%0], [%1], 16;" :: "r"(s), "l"(g) : "memory");
}
__device__ __forceinline__ void ldsm4(uint32_t* r, uint32_t a) {
    asm volatile("ldmatrix.sync.aligned.m8n8.x4.shared.b16 {%0,%1,%2,%3}, [%4];"
                 : "=r"(r[0]), "=r"(r[1]), "=r"(r[2]), "=r"(r[3]) : "r"(a));
}
__device__ __forceinline__ void mma16816(float* c, const uint32_t* a, const uint32_t* b) {
    asm volatile("mma.sync.aligned.m16n8k16.row.col.f32.bf16.bf16.f32 "
                 "{%0,%1,%2,%3}, {%4,%5,%6,%7}, {%8,%9}, {%0,%1,%2,%3};"
                 : "+f"(c[0]), "+f"(c[1]), "+f"(c[2]), "+f"(c[3])
                 : "r"(a[0]), "r"(a[1]), "r"(a[2]), "r"(a[3]), "r"(b[0]), "r"(b[1]));
}
__device__ __forceinline__ void split2(float v, __nv_bfloat16& h, __nv_bfloat16& l) {
    h = __float2bfloat16_rn(v);
    l = __float2bfloat16_rn(v - __bfloat162float(h));
}
__device__ __forceinline__ void store_pair(__nv_bfloat16* __restrict__ H,
                                           __nv_bfloat16* __restrict__ L,
                                           size_t o, float a, float b) {
    __nv_bfloat16 ah, al, bh, bl;
    split2(a, ah, al); split2(b, bh, bl);
    *(__nv_bfloat162*)(H + o) = __halves2bfloat162(ah, bh);
    *(__nv_bfloat162*)(L + o) = __halves2bfloat162(al, bl);
}

// cp.async one K-chunk (32-wide) of A(128 rows) and B(128 rows), hi+lo, into stage s
template <int K>
__device__ __forceinline__ void load_stage(uint32_t sb, int s, int c, int m0, int n0, int tid,
    const __nv_bfloat16* __restrict__ Ah, const __nv_bfloat16* __restrict__ Al,
    const __nv_bfloat16* __restrict__ Bh, const __nv_bfloat16* __restrict__ Bl)
{
    const int k0 = c * BK;
    const uint32_t stg = sb + s * STG_BYTES;
    #pragma unroll
    for (int r = 0; r < 2; r++) {                       // A: 512 16B-chunks, 2/thread
        const int i = tid + r * 256;
        const int row = i >> 2, ch = i & 3;
        const uint32_t so = stg + row * ROWB + ch * 16;
        const size_t g = (size_t)(m0 + row) * K + k0 + ch * 8;
        cp16(so,           Ah + g);
        cp16(so + A_BYTES, Al + g);
    }
    #pragma unroll
    for (int r = 0; r < 2; r++) {                       // B: 512 16B-chunks, 2/thread
        const int i = tid + r * 256;
        const int row = i >> 2, ch = i & 3;
        const uint32_t so = stg + 2 * A_BYTES + row * ROWB + ch * 16;
        const size_t g = (size_t)(n0 + row) * K + k0 + ch * 8;
        cp16(so,           Bh + g);
        cp16(so + B_BYTES, Bl + g);
    }
    asm volatile("cp.async.commit_group;" ::: "memory");
}

// ---------------------------------------------------------------------------
// hgemm<K, EPI>: C[128 x 128] = A[128 x K] @ B[128 rows, K]^T (split bf16, fp32 acc)
// EPI 0: out = tanh(acc + bias[n])                      (h1)
// EPI 1: t = tanh(acc + bias[n]); out = (1-t^2)*w3[n]   (dpre2)
// EPI 2: out = acc * (1 - h1[m,n]^2)                    (dpre1)
// EPI 3: zp[m, zpColBase + n] += coef*acc; refresh zp hi/lo
// ---------------------------------------------------------------------------
template <int K, int EPI>
__global__ void __launch_bounds__(256, 2) hgemm(
    const __nv_bfloat16* __restrict__ Ah, const __nv_bfloat16* __restrict__ Al,
    const __nv_bfloat16* __restrict__ Bh, const __nv_bfloat16* __restrict__ Bl,
    const float* __restrict__ bias, const float* __restrict__ w3,
    const __nv_bfloat16* __restrict__ h1h, const __nv_bfloat16* __restrict__ h1l,
    __nv_bfloat16* __restrict__ Ohi, __nv_bfloat16* __restrict__ Olo,
    float* __restrict__ zp, __nv_bfloat16* __restrict__ zph, __nv_bfloat16* __restrict__ zpl,
    int zpColBase, float coef)
{
    extern __shared__ char smem[];
    const uint32_t sb = smem_u32(smem);
    const int tid = threadIdx.x, lane = tid & 31, wid = tid >> 5;
    const int warp_m = wid & 3, warp_n = wid >> 2;      // 4 x 2 warp grid, 32x64 warp tile
    const int m0 = blockIdx.y * BM, n0 = blockIdx.x * BN;

    float acc[2][8][4];
    #pragma unroll
    for (int a = 0; a < 2; a++)
        #pragma unroll
        for (int b = 0; b < 8; b++)
            #pragma unroll
            for (int d = 0; d < 4; d++) acc[a][b][d] = 0.f;

    load_stage<K>(sb, 0, 0, m0, n0, tid, Ah, Al, Bh, Bl);

    const int NC = K / BK;
    for (int c = 0; c < NC; c++) {
        if (c + 1 < NC) {
            load_stage<K>(sb, (c + 1) & 1, c + 1, m0, n0, tid, Ah, Al, Bh, Bl);
            asm volatile("cp.async.wait_group 1;" ::: "memory");
        } else {
            asm volatile("cp.async.wait_group 0;" ::: "memory");
        }
        __syncthreads();

        const uint32_t base = sb + (c & 1) * STG_BYTES;
        // A ldmatrix lane address: lanes 0-15 rows m0..15 (k lo-half), 16-31 same rows k hi-half
        const uint32_t aH = base + (warp_m * 32 + (lane & 15)) * ROWB + (lane >> 4) * 16;
        // B ldmatrix x4 covers two n8 tiles: lanes 0-7 n0-7 klo, 8-15 n0-7 khi, 16-23 n8-15 klo, 24-31 khi
        const int nrow = ((lane >> 4) << 3) | (lane & 7);
        const uint32_t bH = base + 2 * A_BYTES + (warp_n * 64 + nrow) * ROWB + ((lane >> 3) & 1) * 16;

        #pragma unroll
        for (int ks = 0; ks < 2; ks++) {
            const uint32_t ko = ks * 32;
            uint32_t ah[2][4], al[2][4], bh[4][4], bl[4][4];
            ldsm4(ah[0], aH + ko);
            ldsm4(ah[1], aH + 16 * ROWB + ko);
            #pragma unroll
            for (int p = 0; p < 4; p++) ldsm4(bh[p], bH + p * 16 * ROWB + ko);
            // split 0: A_hi * B_hi
            #pragma unroll
            for (int mt = 0; mt < 2; mt++)
                #pragma unroll
                for (int p = 0; p < 4; p++) {
                    mma16816(acc[mt][2 * p],     ah[mt], &bh[p][0]);
                    mma16816(acc[mt][2 * p + 1], ah[mt], &bh[p][2]);
                }
            // split 1: A_hi * B_lo
            #pragma unroll
            for (int p = 0; p < 4; p++) ldsm4(bl[p], bH + B_BYTES + p * 16 * ROWB + ko);
            #pragma unroll
            for (int mt = 0; mt < 2; mt++)
                #pragma unroll
                for (int p = 0; p < 4; p++) {
                    mma16816(acc[mt][2 * p],     ah[mt], &bl[p][0]);
                    mma16816(acc[mt][2 * p + 1], ah[mt], &bl[p][2]);
                }
            // split 2: A_lo * B_hi
            ldsm4(al[0], aH + A_BYTES + ko);
            ldsm4(al[1], aH + A_BYTES + 16 * ROWB + ko);
            #pragma unroll
            for (int mt = 0; mt < 2; mt++)
                #pragma unroll
                for (int p = 0; p < 4; p++) {
                    mma16816(acc[mt][2 * p],     al[mt], &bh[p][0]);
                    mma16816(acc[mt][2 * p + 1], al[mt], &bh[p][2]);
                }
        }
        __syncthreads();
    }

    // ---------------- epilogue (acc in registers) ----------------
    const int mbase = m0 + warp_m * 32 + (lane >> 2);
    const int nbase = n0 + warp_n * 64 + 2 * (lane & 3);
    #pragma unroll
    for (int mt = 0; mt < 2; mt++) {
        #pragma unroll
        for (int i2 = 0; i2 < 2; i2++) {
            const int m = mbase + mt * 16 + i2 * 8;
            #pragma unroll
            for (int nt = 0; nt < 8; nt++) {
                const int n = nbase + nt * 8;
                const float v0 = acc[mt][nt][i2 * 2 + 0];
                const float v1 = acc[mt][nt][i2 * 2 + 1];
                if (EPI == 0) {
                    const float r0 = tanh_fast(v0 + __ldg(bias + n));
                    const float r1 = tanh_fast(v1 + __ldg(bias + n + 1));
                    store_pair(Ohi, Olo, (size_t)m * HID + n, r0, r1);
                } else if (EPI == 1) {
                    const float t0 = tanh_fast(v0 + __ldg(bias + n));
                    const float t1 = tanh_fast(v1 + __ldg(bias + n + 1));
                    const float r0 = (1.0f - t0 * t0) * __ldg(w3 + n);
                    const float r1 = (1.0f - t1 * t1) * __ldg(w3 + n + 1);
                    store_pair(Ohi, Olo, (size_t)m * HID + n, r0, r1);
                } else if (EPI == 2) {
                    const size_t o = (size_t)m * HID + n;
                    const __nv_bfloat162 hh = *(const __nv_bfloat162*)(h1h + o);
                    const __nv_bfloat162 hl = *(const __nv_bfloat162*)(h1l + o);
                    const float h0 = __bfloat162float(hh.x) + __bfloat162float(hl.x);
                    const float h1v = __bfloat162float(hh.y) + __bfloat162float(hl.y);
                    store_pair(Ohi, Olo, o, v0 * (1.0f - h0 * h0), v1 * (1.0f - h1v * h1v));
                } else {
                    const size_t o = (size_t)m * ZPD + zpColBase + n;
                    float2 z2 = *(float2*)(zp + o);
                    z2.x += coef * v0;
                    z2.y += coef * v1;
                    *(float2*)(zp + o) = z2;
                    store_pair(zph, zpl, o, z2.x, z2.y);
                }
            }
        }
    }
}

// ---------------- small kernels ----------------
__global__ void __launch_bounds__(256) prep_weights(const float* __restrict__ W1,
                                                    const float* __restrict__ W2)
{
    const int idx = blockIdx.x * 256 + threadIdx.x;     // 0 .. 262143
    {   // W1 (1024 x 256): direct + transposed
        const int k = idx >> 8, n = idx & 255;
        __nv_bfloat16 h, l;
        split2(W1[idx], h, l);
        g_W1dh[idx] = h;            g_W1dl[idx] = l;
        g_W1th[n * ZPD + k] = h;    g_W1tl[n * ZPD + k] = l;
    }
    if (idx < HID * HID) {          // W2 (256 x 256): direct + transposed
        const int k = idx >> 8, n = idx & 255;
        __nv_bfloat16 h, l;
        split2(W2[idx], h, l);
        g_W2dh[idx] = h;            g_W2dl[idx] = l;
        g_W2th[n * HID + k] = h;    g_W2tl[n * HID + k] = l;
    }
}

__global__ void __launch_bounds__(256) init_zp(const float* __restrict__ z)
{
    const int i = blockIdx.x * 256 + threadIdx.x;       // over BATCH*DIMQ/4
    const int m = i / (DIMQ / 4);
    const int c = (i % (DIMQ / 4)) * 4;
    const float4 zv = *(const float4*)&z[(size_t)m * DIMQ + c];
    const size_t oq = (size_t)m * ZPD + c;
    const size_t op = oq + DIMQ;
    *(float4*)&g_zp[oq] = zv;
    *(float4*)&g_zp[op] = make_float4(0.f, 0.f, 0.f, 0.f);
    __align__(8) __nv_bfloat16 h[4], l[4];
    split2(zv.x, h[0], l[0]); split2(zv.y, h[1], l[1]);
    split2(zv.z, h[2], l[2]); split2(zv.w, h[3], l[3]);
    *(uint2*)&g_zph[oq] = *(uint2*)h;
    *(uint2*)&g_zpl[oq] = *(uint2*)l;
    *(uint2*)&g_zph[op] = make_uint2(0u, 0u);
    *(uint2*)&g_zpl[op] = make_uint2(0u, 0u);
}

__global__ void __launch_bounds__(256) write_out(float* __restrict__ out)
{
    const int i = blockIdx.x * 256 + threadIdx.x;
    const int m = i / (DIMQ / 4);
    const int c = (i % (DIMQ / 4)) * 4;
    *(float4*)&out[(size_t)m * DIMQ + c] = *(const float4*)&g_zp[(size_t)m * ZPD + c];
}

// ---------------- launcher ----------------
extern "C" void kernel_launch(void* const* d_in, const int* in_sizes, int n_in,
                              void* d_out, int out_size)
{
    const float* z  = (const float*)d_in[0];
    const float* W1 = (const float*)d_in[1];
    const float* b1 = (const float*)d_in[2];
    const float* W2 = (const float*)d_in[3];
    const float* b2 = (const float*)d_in[4];
    const float* W3 = (const float*)d_in[5];
    // d_in[6] = b3: constant, no gradient contribution.
    float* out = (float*)d_out;

    float* zp;  __nv_bfloat16 *zph, *zpl, *h1h, *h1l, *d2h, *d2l, *d1h, *d1l;
    __nv_bfloat16 *W1th, *W1tl, *W2th, *W2tl, *W1dh, *W1dl, *W2dh, *W2dl;
    cudaGetSymbolAddress((void**)&zp,  g_zp);
    cudaGetSymbolAddress((void**)&zph, g_zph);  cudaGetSymbolAddress((void**)&zpl, g_zpl);
    cudaGetSymbolAddress((void**)&h1h, g_h1h);  cudaGetSymbolAddress((void**)&h1l, g_h1l);
    cudaGetSymbolAddress((void**)&d2h, g_d2h);  cudaGetSymbolAddress((void**)&d2l, g_d2l);
    cudaGetSymbolAddress((void**)&d1h, g_d1h);  cudaGetSymbolAddress((void**)&d1l, g_d1l);
    cudaGetSymbolAddress((void**)&W1th, g_W1th); cudaGetSymbolAddress((void**)&W1tl, g_W1tl);
    cudaGetSymbolAddress((void**)&W2th, g_W2th); cudaGetSymbolAddress((void**)&W2tl, g_W2tl);
    cudaGetSymbolAddress((void**)&W1dh, g_W1dh); cudaGetSymbolAddress((void**)&W1dl, g_W1dl);
    cudaGetSymbolAddress((void**)&W2dh, g_W2dh); cudaGetSymbolAddress((void**)&W2dl, g_W2dl);

    cudaFuncSetAttribute(hgemm<1024, 0>, cudaFuncAttributeMaxDynamicSharedMemorySize, SMEM_SZ);
    cudaFuncSetAttribute(hgemm<256, 1>,  cudaFuncAttributeMaxDynamicSharedMemorySize, SMEM_SZ);
    cudaFuncSetAttribute(hgemm<256, 2>,  cudaFuncAttributeMaxDynamicSharedMemorySize, SMEM_SZ);
    cudaFuncSetAttribute(hgemm<256, 3>,  cudaFuncAttributeMaxDynamicSharedMemorySize, SMEM_SZ);

    const dim3 blk(256);
    const dim3 grid_cp((BATCH * DIMQ / 4) / 256);
    const dim3 g256(HID / BN, BATCH / BM);    // (2, 128)
    const dim3 g512(DIMQ / BN, BATCH / BM);   // (4, 128)

    init_zp<<<grid_cp, blk>>>(z);
    prep_weights<<<ZPD * HID / 256, blk>>>(W1, W2);

    for (int step = 0; step < 3; step++) {
        for (int call = 0; call < 3; call++) {
            // h1 = tanh(zp @ W1 + b1)
            hgemm<1024, 0><<<g256, blk, SMEM_SZ>>>(zph, zpl, W1th, W1tl,
                b1, nullptr, nullptr, nullptr, h1h, h1l, nullptr, nullptr, nullptr, 0, 0.f);
            // d2 = (1 - tanh(h1@W2 + b2)^2) * W3
            hgemm<256, 1><<<g256, blk, SMEM_SZ>>>(h1h, h1l, W2th, W2tl,
                b2, W3, nullptr, nullptr, d2h, d2l, nullptr, nullptr, nullptr, 0, 0.f);
            // d1 = (d2 @ W2^T) * (1 - h1^2)
            hgemm<256, 2><<<g256, blk, SMEM_SZ>>>(d2h, d2l, W2dh, W2dl,
                nullptr, nullptr, h1h, h1l, d1h, d1l, nullptr, nullptr, nullptr, 0, 0.f);
            // fused leapfrog update with g = d1 @ W1^T slice
            if (call == 1) {   // q += dt * g_p  (W1 rows 512..1023)
                hgemm<256, 3><<<g512, blk, SMEM_SZ>>>(d1h, d1l,
                    W1dh + (size_t)DIMQ * HID, W1dl + (size_t)DIMQ * HID,
                    nullptr, nullptr, nullptr, nullptr, nullptr, nullptr,
                    zp, zph, zpl, 0, DTC);
            } else {           // p -= 0.5*dt * g_q  (W1 rows 0..511)
                hgemm<256, 3><<<g512, blk, SMEM_SZ>>>(d1h, d1l, W1dh, W1dl,
                    nullptr, nullptr, nullptr, nullptr, nullptr, nullptr,
                    zp, zph, zpl, DIMQ, -0.5f * DTC);
            }
        }
    }
    write_out<<<grid_cp, blk>>>(out);
}

// round 5
// speedup vs baseline: 4.2572x; 1.8375x over previous
#include <cuda_runtime.h>
#include <cuda_bf16.h>
#include <stdint.h>

#define BATCH 16384
#define DIMQ  512
#define ZPD   1024
#define HID   256
#define DTC   0.1f

#define BM 128
#define XPITCH 528                       // 256 bf16 cols = 512B, pad to 528 (16B mult, bank-stride 132%32=4)
#define X_OFF 0                          // h1, later d1 (in-place)
#define Y_OFF (BM * XPITCH)              // 67584: d2
#define STG_OFF (2 * BM * XPITCH)        // 135168
#define STG_SZ 30720                     // A 10240 (128x80) + B 20480 (256x80)
#define B_OFF 10240
#define SMEM_SZ (STG_OFF + 2 * STG_SZ)   // 196608

// ---------------- device globals (no allocs allowed) ----------------
__device__ float         g_zp [BATCH * ZPD];     // fp32 master [q|p]
__device__ __nv_bfloat16 g_zpb[BATCH * ZPD];     // bf16 mirror (MMA operand)
__device__ __nv_bfloat16 g_W1t[HID * ZPD];       // W1^T [n=256][k=1024]
__device__ __nv_bfloat16 g_W1d[ZPD * HID];       // W1   [n'=1024][h=256]
__device__ __nv_bfloat16 g_W2t[HID * HID];       // W2^T
__device__ __nv_bfloat16 g_W2d[HID * HID];       // W2

// ---------------- helpers ----------------
__device__ __forceinline__ uint32_t smem_u32(const void* p) {
    uint32_t a;
    asm("{ .reg .u64 t; cvta.to.shared.u64 t, %1; cvt.u32.u64 %0, t; }" : "=r"(a) : "l"(p));
    return a;
}
__device__ __forceinline__ float tanh_fast(float x) {
    float y; asm("tanh.approx.f32 %0, %1;" : "=f"(y) : "f"(x)); return y;
}
__device__ __forceinline__ void cp16(uint32_t s, const void* g) {
    asm volatile("cp.async.cg.shared.global [%0], [%1], 16;" :: "r"(s), "l"(g) : "memory");
}
__device__ __forceinline__ void ldsm4(uint32_t* r, uint32_t a) {
    asm volatile("ldmatrix.sync.aligned.m8n8.x4.shared.b16 {%0,%1,%2,%3}, [%4];"
                 : "=r"(r[0]), "=r"(r[1]), "=r"(r[2]), "=r"(r[3]) : "r"(a));
}
__device__ __forceinline__ void mma16816(float* c, const uint32_t* a, const uint32_t* b) {
    asm volatile("mma.sync.aligned.m16n8k16.row.col.f32.bf16.bf16.f32 "
                 "{%0,%1,%2,%3}, {%4,%5,%6,%7}, {%8,%9}, {%0,%1,%2,%3};"
                 : "+f"(c[0]), "+f"(c[1]), "+f"(c[2]), "+f"(c[3])
                 : "r"(a[0]), "r"(a[1]), "r"(a[2]), "r"(a[3]), "r"(b[0]), "r"(b[1]));
}
__device__ __forceinline__ __nv_bfloat162 pack_bf2(float a, float b) {
    return __halves2bfloat162(__float2bfloat16_rn(a), __float2bfloat16_rn(b));
}

// ---------------------------------------------------------------------------
// One GEMM pass: acc[128 x 256] = A[128 x KC] @ B[256 rows, KC]^T
// AGM=true: A streamed from gmem (stride KC). AGM=false: A resident in smem at
// aOff (XPITCH rows). B always streamed from gmem (stride bStride) into staging.
// ---------------------------------------------------------------------------
template <int KC, bool AGM>
__device__ __forceinline__ void gemm_pass(
    uint32_t sb, uint32_t aOff,
    const __nv_bfloat16* __restrict__ Agm,
    const __nv_bfloat16* __restrict__ Bgm, int bStride,
    float (&acc)[2][16][4], int tid)
{
    const int lane = tid & 31, wid = tid >> 5;
    const int wm = wid & 3, wn = wid >> 2;

    #pragma unroll
    for (int a = 0; a < 2; a++)
        #pragma unroll
        for (int b = 0; b < 16; b++)
            #pragma unroll
            for (int d = 0; d < 4; d++) acc[a][b][d] = 0.f;

    auto loadB = [&](int s, int c) {
        const uint32_t stg = sb + STG_OFF + s * STG_SZ + B_OFF;
        #pragma unroll
        for (int r = 0; r < 4; r++) {
            const int i = tid + r * 256;
            const int row = i >> 2, ch = i & 3;
            cp16(stg + row * 80 + ch * 16, Bgm + (size_t)row * bStride + c * 32 + ch * 8);
        }
    };
    auto loadA = [&](int s, int c) {
        if (AGM) {
            const uint32_t stg = sb + STG_OFF + s * STG_SZ;
            #pragma unroll
            for (int r = 0; r < 2; r++) {
                const int i = tid + r * 256;
                const int row = i >> 2, ch = i & 3;
                cp16(stg + row * 80 + ch * 16, Agm + (size_t)row * KC + c * 32 + ch * 8);
            }
        }
    };

    loadA(0, 0); loadB(0, 0);
    asm volatile("cp.async.commit_group;" ::: "memory");

    const int NC = KC / 32;
    for (int c = 0; c < NC; c++) {
        if (c + 1 < NC) {
            loadA((c + 1) & 1, c + 1); loadB((c + 1) & 1, c + 1);
            asm volatile("cp.async.commit_group;" ::: "memory");
            asm volatile("cp.async.wait_group 1;" ::: "memory");
        } else {
            asm volatile("cp.async.wait_group 0;" ::: "memory");
        }
        __syncthreads();

        const uint32_t base = sb + STG_OFF + (c & 1) * STG_SZ;
        #pragma unroll
        for (int ks = 0; ks < 2; ks++) {
            uint32_t a[2][4], b[8][4];
            if (AGM) {
                const uint32_t aa = base + (wm * 32 + (lane & 15)) * 80
                                  + ((lane >> 4) << 4) + ks * 32;
                ldsm4(a[0], aa); ldsm4(a[1], aa + 16 * 80);
            } else {
                const uint32_t aa = sb + aOff + (wm * 32 + (lane & 15)) * XPITCH
                                  + ((lane >> 4) << 4) + (c * 32 + ks * 16) * 2;
                ldsm4(a[0], aa); ldsm4(a[1], aa + 16 * XPITCH);
            }
            const uint32_t bb = base + B_OFF
                + (wn * 128 + ((lane >> 4) << 3) + (lane & 7)) * 80
                + (((lane >> 3) & 1) << 4) + ks * 32;
            #pragma unroll
            for (int p = 0; p < 8; p++) ldsm4(b[p], bb + p * 16 * 80);
            #pragma unroll
            for (int mt = 0; mt < 2; mt++)
                #pragma unroll
                for (int p = 0; p < 8; p++) {
                    mma16816(acc[mt][2 * p],     a[mt], &b[p][0]);
                    mma16816(acc[mt][2 * p + 1], a[mt], &b[p][2]);
                }
        }
        __syncthreads();
    }
}

#define EPI_BEGIN                                                               \
    _Pragma("unroll") for (int mt = 0; mt < 2; mt++)                            \
    _Pragma("unroll") for (int i2 = 0; i2 < 2; i2++) {                          \
        const int m = wm * 32 + mt * 16 + i2 * 8 + (lane >> 2);                 \
        _Pragma("unroll") for (int nt = 0; nt < 16; nt++) {                     \
            const int n = wn * 128 + nt * 8 + 2 * (lane & 3);                   \
            const float v0 = acc[mt][nt][i2 * 2], v1 = acc[mt][nt][i2 * 2 + 1];
#define EPI_END }}

// ---------------------------------------------------------------------------
// Fused gradH + leapfrog update: one CTA owns 128 batch rows end-to-end.
// ---------------------------------------------------------------------------
__global__ void __launch_bounds__(256, 1) fused_grad(
    const float* __restrict__ b1, const float* __restrict__ b2,
    const float* __restrict__ W3, int qpOff, int colBase, float coef)
{
    extern __shared__ char smem[];
    const uint32_t sb = smem_u32(smem);
    const int tid = threadIdx.x, lane = tid & 31, wid = tid >> 5;
    const int wm = wid & 3, wn = wid >> 2;
    const int m0 = blockIdx.x * BM;

    float acc[2][16][4];

    // Stage 1: h1 = tanh(zp @ W1 + b1) -> X
    gemm_pass<ZPD, true>(sb, 0, g_zpb + (size_t)m0 * ZPD, g_W1t, ZPD, acc, tid);
    EPI_BEGIN
        const float t0 = tanh_fast(v0 + __ldg(b1 + n));
        const float t1 = tanh_fast(v1 + __ldg(b1 + n + 1));
        *(__nv_bfloat162*)(smem + X_OFF + m * XPITCH + n * 2) = pack_bf2(t0, t1);
    EPI_END
    __syncthreads();

    // Stage 2: d2 = (1 - tanh(h1@W2 + b2)^2) * W3 -> Y   (A = X)
    gemm_pass<HID, false>(sb, X_OFF, nullptr, g_W2t, HID, acc, tid);
    EPI_BEGIN
        const float t0 = tanh_fast(v0 + __ldg(b2 + n));
        const float t1 = tanh_fast(v1 + __ldg(b2 + n + 1));
        const float r0 = (1.0f - t0 * t0) * __ldg(W3 + n);
        const float r1 = (1.0f - t1 * t1) * __ldg(W3 + n + 1);
        *(__nv_bfloat162*)(smem + Y_OFF + m * XPITCH + n * 2) = pack_bf2(r0, r1);
    EPI_END
    __syncthreads();

    // Stage 3: d1 = (d2 @ W2^T) * (1 - h1^2) -> X in-place   (A = Y)
    gemm_pass<HID, false>(sb, Y_OFF, nullptr, g_W2d, HID, acc, tid);
    EPI_BEGIN
        __nv_bfloat162* xp = (__nv_bfloat162*)(smem + X_OFF + m * XPITCH + n * 2);
        const __nv_bfloat162 hh = *xp;
        const float h0 = __bfloat162float(hh.x), h1v = __bfloat162float(hh.y);
        *xp = pack_bf2(v0 * (1.0f - h0 * h0), v1 * (1.0f - h1v * h1v));
    EPI_END
    __syncthreads();

    // Stage 4: g-half = d1 @ W1[qpOff + ...]^T, leapfrog update of zp (2 passes)
    #pragma unroll 1
    for (int pass = 0; pass < 2; pass++) {
        gemm_pass<HID, false>(sb, X_OFF, nullptr,
                              g_W1d + (size_t)(qpOff + pass * 256) * HID, HID, acc, tid);
        EPI_BEGIN
            const size_t o = (size_t)(m0 + m) * ZPD + colBase + pass * 256 + n;
            float2 z = *(float2*)(g_zp + o);
            z.x += coef * v0;
            z.y += coef * v1;
            *(float2*)(g_zp + o) = z;
            *(__nv_bfloat162*)(g_zpb + o) = pack_bf2(z.x, z.y);
        EPI_END
        __syncthreads();
    }
}

// ---------------- small kernels ----------------
__global__ void __launch_bounds__(256) prep_weights(const float* __restrict__ W1,
                                                    const float* __restrict__ W2)
{
    const int idx = blockIdx.x * 256 + threadIdx.x;     // 0 .. 262143
    {
        const int k = idx >> 8, n = idx & 255;
        const __nv_bfloat16 v = __float2bfloat16_rn(W1[idx]);
        g_W1d[idx] = v;
        g_W1t[n * ZPD + k] = v;
    }
    if (idx < HID * HID) {
        const int k = idx >> 8, n = idx & 255;
        const __nv_bfloat16 v = __float2bfloat16_rn(W2[idx]);
        g_W2d[idx] = v;
        g_W2t[n * HID + k] = v;
    }
}

__global__ void __launch_bounds__(256) init_zp(const float* __restrict__ z)
{
    const int i = blockIdx.x * 256 + threadIdx.x;       // over BATCH*DIMQ/4
    const int m = i / (DIMQ / 4);
    const int c = (i % (DIMQ / 4)) * 4;
    const float4 zv = *(const float4*)&z[(size_t)m * DIMQ + c];
    const size_t oq = (size_t)m * ZPD + c;
    const size_t op = oq + DIMQ;
    *(float4*)&g_zp[oq] = zv;
    *(float4*)&g_zp[op] = make_float4(0.f, 0.f, 0.f, 0.f);
    __nv_bfloat162 b01 = pack_bf2(zv.x, zv.y), b23 = pack_bf2(zv.z, zv.w);
    *(uint2*)&g_zpb[oq] = make_uint2(*(uint32_t*)&b01, *(uint32_t*)&b23);
    *(uint2*)&g_zpb[op] = make_uint2(0u, 0u);
}

__global__ void __launch_bounds__(256) write_out(float* __restrict__ out)
{
    const int i = blockIdx.x * 256 + threadIdx.x;
    const int m = i / (DIMQ / 4);
    const int c = (i % (DIMQ / 4)) * 4;
    *(float4*)&out[(size_t)m * DIMQ + c] = *(const float4*)&g_zp[(size_t)m * ZPD + c];
}

// ---------------- launcher ----------------
extern "C" void kernel_launch(void* const* d_in, const int* in_sizes, int n_in,
                              void* d_out, int out_size)
{
    const float* z  = (const float*)d_in[0];
    const float* W1 = (const float*)d_in[1];
    const float* b1 = (const float*)d_in[2];
    const float* W2 = (const float*)d_in[3];
    const float* b2 = (const float*)d_in[4];
    const float* W3 = (const float*)d_in[5];
    // d_in[6] = b3: constant, no gradient contribution.
    float* out = (float*)d_out;

    static int attr_done = 0;
    cudaFuncSetAttribute(fused_grad, cudaFuncAttributeMaxDynamicSharedMemorySize, SMEM_SZ);
    (void)attr_done;

    const dim3 blk(256);
    const dim3 grid_cp((BATCH * DIMQ / 4) / 256);
    const dim3 grid_f(BATCH / BM);          // 128 CTAs

    init_zp<<<grid_cp, blk>>>(z);
    prep_weights<<<ZPD * HID / 256, blk>>>(W1, W2);

    for (int step = 0; step < 3; step++) {
        // call 0: p -= 0.5*dt * g_q   (g_q: W1 rows 0..511 -> zp cols 512..1023)
        fused_grad<<<grid_f, blk, SMEM_SZ>>>(b1, b2, W3, 0, DIMQ, -0.5f * DTC);
        // call 1: q += dt * g_p       (g_p: W1 rows 512..1023 -> zp cols 0..511)
        fused_grad<<<grid_f, blk, SMEM_SZ>>>(b1, b2, W3, DIMQ, 0, DTC);
        // call 2: p -= 0.5*dt * g_q
        fused_grad<<<grid_f, blk, SMEM_SZ>>>(b1, b2, W3, 0, DIMQ, -0.5f * DTC);
    }
    write_out<<<grid_cp, blk>>>(out);
}

// round 6
// speedup vs baseline: 4.7790x; 1.1226x over previous
#include <cuda_runtime.h>
#include <cuda_bf16.h>
#include <stdint.h>

#define BATCH 16384
#define DIMQ  512
#define ZPD   1024
#define HID   256
#define DTC   0.1f

#define BM 64
#define XPITCH 528                        // 256 bf16 = 512B + 16B pad
#define X_OFF 0                           // h1, then d1 (in-place)
#define XSZ (BM * XPITCH)                 // 33792
#define Y_OFF XSZ                         // d2; also A-staging overlay during stage 1
#define BSTG_OFF (2 * XSZ)                // 67584
#define BSTG_SZ 20480                     // 256 rows x 80B
#define ASTG_SZ 5120                      // 64 rows x 80B
#define SMEM_SZ (BSTG_OFF + 2 * BSTG_SZ)  // 108544 (106KB) -> 2 CTAs/SM

// ---------------- device globals (no allocs allowed) ----------------
__device__ float         g_zp [BATCH * ZPD];     // fp32 master [q|p]
__device__ __nv_bfloat16 g_zpb[BATCH * ZPD];     // bf16 mirror (MMA operand)
__device__ __nv_bfloat16 g_W1t[HID * ZPD];       // W1^T [256][1024]
__device__ __nv_bfloat16 g_W1d[ZPD * HID];       // W1   [1024][256]
__device__ __nv_bfloat16 g_W2t[HID * HID];       // W2^T
__device__ __nv_bfloat16 g_W2d[HID * HID];       // W2

// ---------------- helpers ----------------
__device__ __forceinline__ uint32_t smem_u32(const void* p) {
    uint32_t a;
    asm("{ .reg .u64 t; cvta.to.shared.u64 t, %1; cvt.u32.u64 %0, t; }" : "=r"(a) : "l"(p));
    return a;
}
__device__ __forceinline__ float tanh_fast(float x) {
    float y; asm("tanh.approx.f32 %0, %1;" : "=f"(y) : "f"(x)); return y;
}
__device__ __forceinline__ void cp16(uint32_t s, const void* g) {
    asm volatile("cp.async.cg.shared.global [%0], [%1], 16;" :: "r"(s), "l"(g) : "memory");
}
__device__ __forceinline__ void ldsm4(uint32_t* r, uint32_t a) {
    asm volatile("ldmatrix.sync.aligned.m8n8.x4.shared.b16 {%0,%1,%2,%3}, [%4];"
                 : "=r"(r[0]), "=r"(r[1]), "=r"(r[2]), "=r"(r[3]) : "r"(a));
}
__device__ __forceinline__ void mma16816(float* c, const uint32_t* a, const uint32_t* b) {
    asm volatile("mma.sync.aligned.m16n8k16.row.col.f32.bf16.bf16.f32 "
                 "{%0,%1,%2,%3}, {%4,%5,%6,%7}, {%8,%9}, {%0,%1,%2,%3};"
                 : "+f"(c[0]), "+f"(c[1]), "+f"(c[2]), "+f"(c[3])
                 : "r"(a[0]), "r"(a[1]), "r"(a[2]), "r"(a[3]), "r"(b[0]), "r"(b[1]));
}
__device__ __forceinline__ __nv_bfloat162 pack_bf2(float a, float b) {
    return __halves2bfloat162(__float2bfloat16_rn(a), __float2bfloat16_rn(b));
}

// ---------------------------------------------------------------------------
// One GEMM pass: acc[64 x 256] = A[64 x KC] @ B[256 rows, KC]^T
// AGM=true: A streamed from gmem into double-buffered staging at aOff.
// AGM=false: A resident in smem at aOff (XPITCH-stride rows).
// B streamed from gmem (stride bStride) into BSTG double buffer.
// ---------------------------------------------------------------------------
template <int KC, bool AGM>
__device__ __forceinline__ void gemm_pass(
    uint32_t sb, uint32_t aOff,
    const __nv_bfloat16* __restrict__ Agm,
    const __nv_bfloat16* __restrict__ Bgm, int bStride,
    float (&acc)[2][8][4], int tid)
{
    const int lane = tid & 31, wid = tid >> 5;
    const int wm = wid & 1, wn = wid >> 1;        // 2 x 4 warps, 32x64 warp tile

    #pragma unroll
    for (int a = 0; a < 2; a++)
        #pragma unroll
        for (int b = 0; b < 8; b++)
            #pragma unroll
            for (int d = 0; d < 4; d++) acc[a][b][d] = 0.f;

    auto loadB = [&](int s, int c) {
        const uint32_t stg = sb + BSTG_OFF + s * BSTG_SZ;
        #pragma unroll
        for (int r = 0; r < 4; r++) {
            const int i = tid + r * 256;
            const int row = i >> 2, ch = i & 3;
            cp16(stg + row * 80 + ch * 16, Bgm + (size_t)row * bStride + c * 32 + ch * 8);
        }
    };
    auto loadA = [&](int s, int c) {
        if (AGM) {
            const uint32_t stg = sb + aOff + s * ASTG_SZ;
            const int row = tid >> 2, ch = tid & 3;      // 64 rows x 4 chunks = 256
            cp16(stg + row * 80 + ch * 16, Agm + (size_t)row * KC + c * 32 + ch * 8);
        }
    };

    loadA(0, 0); loadB(0, 0);
    asm volatile("cp.async.commit_group;" ::: "memory");

    const int NC = KC / 32;
    for (int c = 0; c < NC; c++) {
        if (c + 1 < NC) {
            loadA((c + 1) & 1, c + 1); loadB((c + 1) & 1, c + 1);
            asm volatile("cp.async.commit_group;" ::: "memory");
            asm volatile("cp.async.wait_group 1;" ::: "memory");
        } else {
            asm volatile("cp.async.wait_group 0;" ::: "memory");
        }
        __syncthreads();

        const uint32_t bbase = sb + BSTG_OFF + (c & 1) * BSTG_SZ;
        #pragma unroll
        for (int ks = 0; ks < 2; ks++) {
            uint32_t a[2][4], b[4][4];
            if (AGM) {
                const uint32_t aa = sb + aOff + (c & 1) * ASTG_SZ
                                  + (wm * 32 + (lane & 15)) * 80
                                  + ((lane >> 4) << 4) + ks * 32;
                ldsm4(a[0], aa); ldsm4(a[1], aa + 16 * 80);
            } else {
                const uint32_t aa = sb + aOff + (wm * 32 + (lane & 15)) * XPITCH
                                  + ((lane >> 4) << 4) + (c * 32 + ks * 16) * 2;
                ldsm4(a[0], aa); ldsm4(a[1], aa + 16 * XPITCH);
            }
            const uint32_t bb = bbase
                + (wn * 64 + ((lane >> 4) << 3) + (lane & 7)) * 80
                + (((lane >> 3) & 1) << 4) + ks * 32;
            #pragma unroll
            for (int p = 0; p < 4; p++) ldsm4(b[p], bb + p * 16 * 80);
            #pragma unroll
            for (int mt = 0; mt < 2; mt++)
                #pragma unroll
                for (int p = 0; p < 4; p++) {
                    mma16816(acc[mt][2 * p],     a[mt], &b[p][0]);
                    mma16816(acc[mt][2 * p + 1], a[mt], &b[p][2]);
                }
        }
        __syncthreads();
    }
}

#define EPI_BEGIN                                                               \
    _Pragma("unroll") for (int mt = 0; mt < 2; mt++)                            \
    _Pragma("unroll") for (int i2 = 0; i2 < 2; i2++) {                          \
        const int m = wm * 32 + mt * 16 + i2 * 8 + (lane >> 2);                 \
        _Pragma("unroll") for (int nt = 0; nt < 8; nt++) {                      \
            const int n = wn * 64 + nt * 8 + 2 * (lane & 3);                    \
            const float v0 = acc[mt][nt][i2 * 2], v1 = acc[mt][nt][i2 * 2 + 1];
#define EPI_END }}

// ---------------------------------------------------------------------------
// Fused gradH + leapfrog update: one CTA owns 64 batch rows end-to-end.
// ---------------------------------------------------------------------------
__global__ void __launch_bounds__(256, 2) fused_grad(
    const float* __restrict__ b1, const float* __restrict__ b2,
    const float* __restrict__ W3, int qpOff, int colBase, float coef)
{
    extern __shared__ char smem[];
    const uint32_t sb = smem_u32(smem);
    const int tid = threadIdx.x, lane = tid & 31, wid = tid >> 5;
    const int wm = wid & 1, wn = wid >> 1;
    const int m0 = blockIdx.x * BM;

    float acc[2][8][4];

    // Stage 1: h1 = tanh(zp @ W1 + b1) -> X   (A from gmem, staged in Y overlay)
    gemm_pass<ZPD, true>(sb, Y_OFF, g_zpb + (size_t)m0 * ZPD, g_W1t, ZPD, acc, tid);
    EPI_BEGIN
        const float t0 = tanh_fast(v0 + __ldg(b1 + n));
        const float t1 = tanh_fast(v1 + __ldg(b1 + n + 1));
        *(__nv_bfloat162*)(smem + X_OFF + m * XPITCH + n * 2) = pack_bf2(t0, t1);
    EPI_END
    __syncthreads();

    // Stage 2: d2 = (1 - tanh(h1@W2 + b2)^2) * W3 -> Y   (A = X resident)
    gemm_pass<HID, false>(sb, X_OFF, nullptr, g_W2t, HID, acc, tid);
    EPI_BEGIN
        const float t0 = tanh_fast(v0 + __ldg(b2 + n));
        const float t1 = tanh_fast(v1 + __ldg(b2 + n + 1));
        const float r0 = (1.0f - t0 * t0) * __ldg(W3 + n);
        const float r1 = (1.0f - t1 * t1) * __ldg(W3 + n + 1);
        *(__nv_bfloat162*)(smem + Y_OFF + m * XPITCH + n * 2) = pack_bf2(r0, r1);
    EPI_END
    __syncthreads();

    // Stage 3: d1 = (d2 @ W2^T) * (1 - h1^2) -> X in-place   (A = Y resident)
    gemm_pass<HID, false>(sb, Y_OFF, nullptr, g_W2d, HID, acc, tid);
    EPI_BEGIN
        __nv_bfloat162* xp = (__nv_bfloat162*)(smem + X_OFF + m * XPITCH + n * 2);
        const __nv_bfloat162 hh = *xp;
        const float h0 = __bfloat162float(hh.x), h1v = __bfloat162float(hh.y);
        *xp = pack_bf2(v0 * (1.0f - h0 * h0), v1 * (1.0f - h1v * h1v));
    EPI_END
    __syncthreads();

    // Stage 4: g-half = d1 @ W1[qpOff..]^T, fused leapfrog zp update (2 passes)
    #pragma unroll 1
    for (int pass = 0; pass < 2; pass++) {
        gemm_pass<HID, false>(sb, X_OFF, nullptr,
                              g_W1d + (size_t)(qpOff + pass * 256) * HID, HID, acc, tid);
        EPI_BEGIN
            const size_t o = (size_t)(m0 + m) * ZPD + colBase + pass * 256 + n;
            float2 z = *(float2*)(g_zp + o);
            z.x += coef * v0;
            z.y += coef * v1;
            *(float2*)(g_zp + o) = z;
            *(__nv_bfloat162*)(g_zpb + o) = pack_bf2(z.x, z.y);
        EPI_END
        __syncthreads();
    }
}

// ---------------- small kernels ----------------
__global__ void __launch_bounds__(256) prep_weights(const float* __restrict__ W1,
                                                    const float* __restrict__ W2)
{
    const int idx = blockIdx.x * 256 + threadIdx.x;     // 0 .. 262143
    {
        const int k = idx >> 8, n = idx & 255;
        const __nv_bfloat16 v = __float2bfloat16_rn(W1[idx]);
        g_W1d[idx] = v;
        g_W1t[n * ZPD + k] = v;
    }
    if (idx < HID * HID) {
        const int k = idx >> 8, n = idx & 255;
        const __nv_bfloat16 v = __float2bfloat16_rn(W2[idx]);
        g_W2d[idx] = v;
        g_W2t[n * HID + k] = v;
    }
}

__global__ void __launch_bounds__(256) init_zp(const float* __restrict__ z)
{
    const int i = blockIdx.x * 256 + threadIdx.x;       // over BATCH*DIMQ/4
    const int m = i / (DIMQ / 4);
    const int c = (i % (DIMQ / 4)) * 4;
    const float4 zv = *(const float4*)&z[(size_t)m * DIMQ + c];
    const size_t oq = (size_t)m * ZPD + c;
    const size_t op = oq + DIMQ;
    *(float4*)&g_zp[oq] = zv;
    *(float4*)&g_zp[op] = make_float4(0.f, 0.f, 0.f, 0.f);
    __nv_bfloat162 b01 = pack_bf2(zv.x, zv.y), b23 = pack_bf2(zv.z, zv.w);
    *(uint2*)&g_zpb[oq] = make_uint2(*(uint32_t*)&b01, *(uint32_t*)&b23);
    *(uint2*)&g_zpb[op] = make_uint2(0u, 0u);
}

__global__ void __launch_bounds__(256) write_out(float* __restrict__ out)
{
    const int i = blockIdx.x * 256 + threadIdx.x;
    const int m = i / (DIMQ / 4);
    const int c = (i % (DIMQ / 4)) * 4;
    *(float4*)&out[(size_t)m * DIMQ + c] = *(const float4*)&g_zp[(size_t)m * ZPD + c];
}

// ---------------- launcher ----------------
extern "C" void kernel_launch(void* const* d_in, const int* in_sizes, int n_in,
                              void* d_out, int out_size)
{
    const float* z  = (const float*)d_in[0];
    const float* W1 = (const float*)d_in[1];
    const float* b1 = (const float*)d_in[2];
    const float* W2 = (const float*)d_in[3];
    const float* b2 = (const float*)d_in[4];
    const float* W3 = (const float*)d_in[5];
    // d_in[6] = b3: constant, no gradient contribution.
    float* out = (float*)d_out;

    cudaFuncSetAttribute(fused_grad, cudaFuncAttributeMaxDynamicSharedMemorySize, SMEM_SZ);

    const dim3 blk(256);
    const dim3 grid_cp((BATCH * DIMQ / 4) / 256);
    const dim3 grid_f(BATCH / BM);          // 256 CTAs -> 2 per SM

    init_zp<<<grid_cp, blk>>>(z);
    prep_weights<<<ZPD * HID / 256, blk>>>(W1, W2);

    for (int step = 0; step < 3; step++) {
        // call 0: p -= 0.5*dt * g_q   (g_q: W1 rows 0..511 -> zp cols 512..1023)
        fused_grad<<<grid_f, blk, SMEM_SZ>>>(b1, b2, W3, 0, DIMQ, -0.5f * DTC);
        // call 1: q += dt * g_p       (g_p: W1 rows 512..1023 -> zp cols 0..511)
        fused_grad<<<grid_f, blk, SMEM_SZ>>>(b1, b2, W3, DIMQ, 0, DTC);
        // call 2: p -= 0.5*dt * g_q
        fused_grad<<<grid_f, blk, SMEM_SZ>>>(b1, b2, W3, 0, DIMQ, -0.5f * DTC);
    }
    write_out<<<grid_cp, blk>>>(out);
}